// round 2
// baseline (speedup 1.0000x reference)
#include <cuda_runtime.h>
#include <cstdint>
#include <cstdio>

#define BATCH   4
#define ORIG_   256
#define NORIG   (ORIG_*ORIG_)     // 65536
#define DOWN_   128
#define NDOWN   (DOWN_*DOWN_)     // 16384
#define FEAT    256
#define TILE_M  128
#define THREADS 512
#define A_STRIDE 260              // 260 % 32 == 4 -> conflict-free frag loads
#define W_STRIDE 36               // 36  % 32 == 4

#define SMEM_FLOATS (TILE_M*A_STRIDE + FEAT*W_STRIDE + FEAT + FEAT + 2*TILE_M*2)
#define SMEM_BYTES  (SMEM_FLOATS*4)

__device__ __forceinline__ float tf32r(float x){
    float r; asm("cvt.rna.tf32.f32 %0, %1;" : "=f"(r) : "f"(x)); return r;
}

// MODE 0: down path. src = H_orig. A[dj][f] = 0.5*sum of 4 orig rows of block (di,dj).
//         out = H_new_updated region, dense store.
// MODE 1: up path.  src = H_down. A[dj][f] = 0.5*H_down row. Each LN'd row stored to
//         4 orig destinations (replica structure of the scatter).
template<int MODE>
__global__ __launch_bounds__(THREADS, 1)
void fused_gemm_ln(const float* __restrict__ src,
                   const float* __restrict__ W,
                   const float* __restrict__ gvec,
                   const float* __restrict__ bvec,
                   float* __restrict__ out)
{
    extern __shared__ float smem[];
    float* A_s   = smem;                         // 128*260
    float* Wc_s  = A_s  + TILE_M*A_STRIDE;       // 256*36
    float* gs    = Wc_s + FEAT*W_STRIDE;         // 256
    float* bs    = gs   + FEAT;                  // 256
    float* red_s = bs   + FEAT;                  // 2*128*2

    const int tid  = threadIdx.x;
    const int lane = tid & 31;
    const int w    = tid >> 5;
    const int rg   = w & 7;        // row-group (16 rows each)
    const int ch   = w >> 3;       // column half (128 cols each)

    const int tile = blockIdx.x;   // 512 tiles = 4 batches * 128 row-tiles
    const int b    = tile >> 7;
    const int di   = tile & 127;

    // ---------------- Phase 1: build A tile in SMEM (tf32-rounded) --------------
    {
        const float4* s4 = (const float4*)src;
        if (MODE == 0) {
            const size_t rowbase = ((size_t)b*NORIG + (size_t)(2*di)*ORIG_);
            for (int i = tid; i < TILE_M*64; i += THREADS){
                int dj = i >> 6, q = i & 63;
                const float4* p = s4 + (rowbase + (size_t)(2*dj))*64 + q;
                float4 v0 = p[0];
                float4 v1 = p[64];             // node+1
                float4 v2 = p[ORIG_*64];       // node+256 (next orig grid row)
                float4 v3 = p[ORIG_*64 + 64];
                float4 o;
                o.x = tf32r(0.5f*((v0.x+v1.x)+(v2.x+v3.x)));
                o.y = tf32r(0.5f*((v0.y+v1.y)+(v2.y+v3.y)));
                o.z = tf32r(0.5f*((v0.z+v1.z)+(v2.z+v3.z)));
                o.w = tf32r(0.5f*((v0.w+v1.w)+(v2.w+v3.w)));
                *(float4*)&A_s[dj*A_STRIDE + q*4] = o;
            }
        } else {
            const size_t rowbase = ((size_t)b*NDOWN + (size_t)di*TILE_M);
            for (int i = tid; i < TILE_M*64; i += THREADS){
                int dj = i >> 6, q = i & 63;
                float4 v = s4[(rowbase + dj)*64 + q];
                float4 o;
                o.x = tf32r(0.5f*v.x); o.y = tf32r(0.5f*v.y);
                o.z = tf32r(0.5f*v.z); o.w = tf32r(0.5f*v.w);
                *(float4*)&A_s[dj*A_STRIDE + q*4] = o;
            }
        }
        if (tid < FEAT){ gs[tid] = gvec[tid]; bs[tid] = bvec[tid]; }
    }

    // ---------------- Phase 2: GEMM via mma.sync tf32 ---------------------------
    float acc[16][4];
    #pragma unroll
    for (int nt = 0; nt < 16; nt++){
        acc[nt][0]=0.f; acc[nt][1]=0.f; acc[nt][2]=0.f; acc[nt][3]=0.f;
    }

    const int arow = rg*16 + (lane>>2);   // rows arow and arow+8
    const int kq   = lane & 3;

    for (int kc = 0; kc < 8; kc++){
        __syncthreads();   // A ready (1st iter); Wc reads from prev iter done
        // load W chunk: Wc_s[n][0..31] = W[n][kc*32 .. +31], tf32-rounded
        for (int i = tid; i < FEAT*8; i += THREADS){
            int n = i >> 3, q = i & 7;
            float4 v = *(const float4*)&W[(size_t)n*FEAT + kc*32 + q*4];
            float4 o;
            o.x = tf32r(v.x); o.y = tf32r(v.y); o.z = tf32r(v.z); o.w = tf32r(v.w);
            *(float4*)&Wc_s[n*W_STRIDE + q*4] = o;
        }
        __syncthreads();
        #pragma unroll
        for (int ks = 0; ks < 4; ks++){
            const int kk = kc*32 + ks*8;
            uint32_t a0 = __float_as_uint(A_s[ arow   *A_STRIDE + kk + kq    ]);
            uint32_t a1 = __float_as_uint(A_s[(arow+8)*A_STRIDE + kk + kq    ]);
            uint32_t a2 = __float_as_uint(A_s[ arow   *A_STRIDE + kk + kq + 4]);
            uint32_t a3 = __float_as_uint(A_s[(arow+8)*A_STRIDE + kk + kq + 4]);
            const int kw = ks*8;
            #pragma unroll
            for (int nt = 0; nt < 16; nt++){
                const int n = ch*128 + nt*8 + (lane>>2);
                uint32_t b0 = __float_as_uint(Wc_s[n*W_STRIDE + kw + kq    ]);
                uint32_t b1 = __float_as_uint(Wc_s[n*W_STRIDE + kw + kq + 4]);
                asm volatile(
                    "mma.sync.aligned.m16n8k8.row.col.f32.tf32.tf32.f32 "
                    "{%0,%1,%2,%3}, {%4,%5,%6,%7}, {%8,%9}, {%0,%1,%2,%3};\n"
                    : "+f"(acc[nt][0]), "+f"(acc[nt][1]),
                      "+f"(acc[nt][2]), "+f"(acc[nt][3])
                    : "r"(a0), "r"(a1), "r"(a2), "r"(a3), "r"(b0), "r"(b1));
            }
        }
    }

    // ---------------- Phase 3: LayerNorm reduction ------------------------------
    float sA=0.f, qA=0.f, sB=0.f, qB=0.f;
    #pragma unroll
    for (int nt = 0; nt < 16; nt++){
        float x0=acc[nt][0], x1=acc[nt][1], x2=acc[nt][2], x3=acc[nt][3];
        sA += x0+x1; qA += x0*x0 + x1*x1;
        sB += x2+x3; qB += x2*x2 + x3*x3;
    }
    #pragma unroll
    for (int o = 1; o < 4; o <<= 1){
        sA += __shfl_xor_sync(0xffffffffu, sA, o);
        qA += __shfl_xor_sync(0xffffffffu, qA, o);
        sB += __shfl_xor_sync(0xffffffffu, sB, o);
        qB += __shfl_xor_sync(0xffffffffu, qB, o);
    }
    if ((lane & 3) == 0){
        red_s[ch*2*TILE_M +  arow   *2    ] = sA;
        red_s[ch*2*TILE_M +  arow   *2 + 1] = qA;
        red_s[ch*2*TILE_M + (arow+8)*2    ] = sB;
        red_s[ch*2*TILE_M + (arow+8)*2 + 1] = qB;
    }
    __syncthreads();

    float s0 = red_s[arow*2    ] + red_s[2*TILE_M + arow*2    ];
    float q0 = red_s[arow*2 + 1] + red_s[2*TILE_M + arow*2 + 1];
    float mA = s0 * (1.f/FEAT);
    float rA = rsqrtf(fmaxf(q0*(1.f/FEAT) - mA*mA, 0.f) + 1e-5f);

    float s1 = red_s[(arow+8)*2    ] + red_s[2*TILE_M + (arow+8)*2    ];
    float q1 = red_s[(arow+8)*2 + 1] + red_s[2*TILE_M + (arow+8)*2 + 1];
    float mB = s1 * (1.f/FEAT);
    float rB = rsqrtf(fmaxf(q1*(1.f/FEAT) - mB*mB, 0.f) + 1e-5f);

    // ---------------- Phase 4: scale/shift + ReLU + store -----------------------
    if (MODE == 0) {
        const size_t ob = ((size_t)b*NDOWN + (size_t)di*TILE_M);
        float* pA = out + (ob + arow    )*FEAT;
        float* pB = out + (ob + arow + 8)*FEAT;
        #pragma unroll
        for (int nt = 0; nt < 16; nt++){
            int col = ch*128 + nt*8 + 2*kq;
            float g0=gs[col], g1=gs[col+1], d0=bs[col], d1=bs[col+1];
            float2 va, vb;
            va.x = fmaxf(fmaf((acc[nt][0]-mA)*rA, g0, d0), 0.f);
            va.y = fmaxf(fmaf((acc[nt][1]-mA)*rA, g1, d1), 0.f);
            vb.x = fmaxf(fmaf((acc[nt][2]-mB)*rB, g0, d0), 0.f);
            vb.y = fmaxf(fmaf((acc[nt][3]-mB)*rB, g1, d1), 0.f);
            *(float2*)&pA[col] = va;
            *(float2*)&pB[col] = vb;
        }
    } else {
        const size_t nb = (size_t)b*NORIG;
        const size_t baseA = (nb + (size_t)(2*di)*ORIG_ + (size_t)(2* arow   ))*FEAT;
        const size_t baseB = (nb + (size_t)(2*di)*ORIG_ + (size_t)(2*(arow+8)))*FEAT;
        #pragma unroll
        for (int nt = 0; nt < 16; nt++){
            int col = ch*128 + nt*8 + 2*kq;
            float g0=gs[col], g1=gs[col+1], d0=bs[col], d1=bs[col+1];
            float2 va, vb;
            va.x = fmaxf(fmaf((acc[nt][0]-mA)*rA, g0, d0), 0.f);
            va.y = fmaxf(fmaf((acc[nt][1]-mA)*rA, g1, d1), 0.f);
            vb.x = fmaxf(fmaf((acc[nt][2]-mB)*rB, g0, d0), 0.f);
            vb.y = fmaxf(fmaf((acc[nt][3]-mB)*rB, g1, d1), 0.f);
            // 4 replicated destinations: (+0), (+1 node), (+1 grid row), (both)
            *(float2*)&out[baseA + col              ] = va;
            *(float2*)&out[baseA + col + FEAT       ] = va;
            *(float2*)&out[baseA + col + ORIG_*FEAT ] = va;
            *(float2*)&out[baseA + col + ORIG_*FEAT + FEAT] = va;
            *(float2*)&out[baseB + col              ] = vb;
            *(float2*)&out[baseB + col + FEAT       ] = vb;
            *(float2*)&out[baseB + col + ORIG_*FEAT ] = vb;
            *(float2*)&out[baseB + col + ORIG_*FEAT + FEAT] = vb;
        }
    }
}

extern "C" void kernel_launch(void* const* d_in, const int* in_sizes, int n_in,
                              void* d_out, int out_size)
{
    const float* H_orig = (const float*)d_in[0];
    const float* H_down = (const float*)d_in[1];
    const float* W_o2n  = (const float*)d_in[2];
    const float* W_n2o  = (const float*)d_in[3];
    const float* g_o2n  = (const float*)d_in[4];
    const float* b_o2n  = (const float*)d_in[5];
    const float* g_n2o  = (const float*)d_in[6];
    const float* b_n2o  = (const float*)d_in[7];

    float* out       = (float*)d_out;
    float* out_orig  = out;                                        // (4,65536,256)
    float* out_new   = out + (size_t)BATCH*NORIG*FEAT;             // (4,16384,256)

    cudaFuncSetAttribute(fused_gemm_ln<0>,
                         cudaFuncAttributeMaxDynamicSharedMemorySize, SMEM_BYTES);
    cudaFuncSetAttribute(fused_gemm_ln<1>,
                         cudaFuncAttributeMaxDynamicSharedMemorySize, SMEM_BYTES);

    const int grid = BATCH * (NDOWN / TILE_M);   // 512
    fused_gemm_ln<0><<<grid, THREADS, SMEM_BYTES>>>(H_orig, W_o2n, g_o2n, b_o2n, out_new);
    fused_gemm_ln<1><<<grid, THREADS, SMEM_BYTES>>>(H_down, W_n2o, g_n2o, b_n2o, out_orig);
}

// round 3
// speedup vs baseline: 2.4749x; 2.4749x over previous
#include <cuda_runtime.h>
#include <cstdint>

#define BATCH   4
#define ORIG_   256
#define NORIG   (ORIG_*ORIG_)     // 65536
#define DOWN_   128
#define NDOWN   (DOWN_*DOWN_)     // 16384
#define FEAT    256
#define TILE_M  64
#define THREADS 512

// SMEM layout (floats)
#define A_STRIDE 36               // 8*36 mod 32 -> (4r+q) distinct: conflict-free a-frags
#define W_STRIDE 264              // k-major W: (8q+r) distinct: conflict-free b-frags
#define A_BUF    (TILE_M*A_STRIDE)        // 2304
#define W_BUF    (32*W_STRIDE)            // 8448
#define OFF_W    (2*A_BUF)                // 4608
#define OFF_G    (OFF_W + 2*W_BUF)        // 21504
#define OFF_B    (OFF_G + FEAT)           // 21760
#define OFF_RED  (OFF_B + FEAT)           // 22016
#define SM_FLOATS (OFF_RED + 4*TILE_M*2)  // 22528
#define SM_BYTES  (SM_FLOATS*4)           // 90112

__device__ float Wt_dev[2][FEAT*FEAT];   // tf32-rounded, k-major weights

__device__ __forceinline__ float tf32r(float x){
    float r; asm("cvt.rna.tf32.f32 %0, %1;" : "=f"(r) : "f"(x)); return r;
}
__device__ __forceinline__ void cpasync16(uint32_t dst, const void* src){
    asm volatile("cp.async.cg.shared.global [%0], [%1], 16;\n" :: "r"(dst), "l"(src));
}
__device__ __forceinline__ void cpcommit(){ asm volatile("cp.async.commit_group;\n" ::: "memory"); }
__device__ __forceinline__ void cpwait0(){ asm volatile("cp.async.wait_group 0;\n" ::: "memory"); }

// ---- prep: Wt[k][n] = tf32_rn(W[n][k]) for both weights (512 KB, stays in L2) ----
__global__ void prep_w(const float* __restrict__ W0, const float* __restrict__ W1){
    __shared__ float t[32][33];
    const float* W  = blockIdx.z ? W1 : W0;
    float*       Wt = Wt_dev[blockIdx.z];
    int bk = blockIdx.x*32, bn = blockIdx.y*32;
    int tx = threadIdx.x, ty = threadIdx.y;
    #pragma unroll
    for (int j = 0; j < 32; j += 8)
        t[ty+j][tx] = W[(size_t)(bn+ty+j)*FEAT + bk + tx];
    __syncthreads();
    #pragma unroll
    for (int j = 0; j < 32; j += 8)
        Wt[(size_t)(bk+ty+j)*FEAT + bn + tx] = tf32r(t[tx][ty+j]);
}

// ---- fused GEMM + LayerNorm + ReLU (+ fanout) for both paths ----
// mode = blockIdx.x & 1 : 0 = down path (H_orig gather-sum -> H_new), 1 = up path (H_down -> H_orig fanout x4)
// NOTE: the 0.5 adjacency value is dropped: LayerNorm is invariant to uniform row scaling.
__global__ __launch_bounds__(THREADS, 2)
void fused(const float* __restrict__ Ho, const float* __restrict__ Hd,
           const float* __restrict__ g0v, const float* __restrict__ b0v,
           const float* __restrict__ g1v, const float* __restrict__ b1v,
           float* __restrict__ outbase)
{
    extern __shared__ float sm[];
    float* Asm = sm;
    float* Wsm = sm + OFF_W;
    float* gs  = sm + OFF_G;
    float* bs  = sm + OFF_B;
    float* red = sm + OFF_RED;

    const int tid  = threadIdx.x;
    const int lane = tid & 31;
    const int w    = tid >> 5;
    const int rg   = w & 3;        // row group (16 rows)
    const int ch   = w >> 2;       // column quarter (64 cols)
    const int ly   = lane >> 2;
    const int kq   = lane & 3;

    const int mode = blockIdx.x & 1;
    const int tile = blockIdx.x >> 1;      // 0..1023
    const int b    = tile >> 8;
    const int rem  = tile & 255;
    const int di   = rem >> 1;             // down-grid row
    const int half = rem & 1;              // which 64 of the 128 dj's

    const float* gv = mode ? g1v : g0v;
    const float* bv = mode ? b1v : b0v;
    const float* Wt = Wt_dev[mode];
    if (tid < FEAT){ gs[tid] = gv[tid]; bs[tid] = bv[tid]; }

    const uint32_t smb = (uint32_t)__cvta_generic_to_shared(sm);

    // per-thread A-load coords
    const int dj = tid >> 3, q = tid & 7;        // 64 rows x 8 float4
    const size_t orow = (size_t)b*NORIG + (size_t)(2*di)*ORIG_ + (size_t)2*(half*64 + dj);
    const size_t drow = (size_t)b*NDOWN + (size_t)(di*DOWN_ + half*64 + dj);

    float acc[8][4];
    #pragma unroll
    for (int nt = 0; nt < 8; nt++){ acc[nt][0]=0.f; acc[nt][1]=0.f; acc[nt][2]=0.f; acc[nt][3]=0.f; }

    // ---- chunk loaders ----
    auto loadW = [&](int kc){
        const float* src = Wt + (size_t)(kc*32)*FEAT;
        uint32_t base = smb + 4u*(OFF_W + (kc&1)*W_BUF);
        #pragma unroll
        for (int j = 0; j < 4; j++){
            int idx = tid + j*THREADS;           // 0..2047
            int k = idx >> 6, n4 = idx & 63;
            cpasync16(base + 4u*(k*W_STRIDE + n4*4), src + (size_t)k*FEAT + n4*4);
        }
    };
    auto loadA = [&](int kc){
        if (mode == 0){
            const float4* p = (const float4*)Ho + orow*64 + (kc*8 + q);
            float4 v0 = __ldcs(p);
            float4 v1 = __ldcs(p + 64);
            float4 v2 = __ldcs(p + ORIG_*64);
            float4 v3 = __ldcs(p + ORIG_*64 + 64);
            float4 s;
            s.x = tf32r((v0.x+v1.x)+(v2.x+v3.x));
            s.y = tf32r((v0.y+v1.y)+(v2.y+v3.y));
            s.z = tf32r((v0.z+v1.z)+(v2.z+v3.z));
            s.w = tf32r((v0.w+v1.w)+(v2.w+v3.w));
            *(float4*)&Asm[(kc&1)*A_BUF + dj*A_STRIDE + q*4] = s;
        } else {
            cpasync16(smb + 4u*((kc&1)*A_BUF + dj*A_STRIDE + q*4),
                      Hd + drow*FEAT + kc*32 + q*4);
        }
    };

    // ---- pipelined mainloop ----
    loadW(0); loadA(0); cpcommit();

    for (int kc = 0; kc < 8; kc++){
        cpwait0();
        __syncthreads();
        if (kc < 7){ loadW(kc+1); loadA(kc+1); cpcommit(); }

        const float* Ab = Asm + (kc&1)*A_BUF;
        const float* Wb = Wsm + (kc&1)*W_BUF;
        #pragma unroll
        for (int ks = 0; ks < 4; ks++){
            const int kk = ks*8;
            uint32_t a0 = __float_as_uint(Ab[(rg*16+ly  )*A_STRIDE + kk+kq  ]);
            uint32_t a1 = __float_as_uint(Ab[(rg*16+ly+8)*A_STRIDE + kk+kq  ]);
            uint32_t a2 = __float_as_uint(Ab[(rg*16+ly  )*A_STRIDE + kk+kq+4]);
            uint32_t a3 = __float_as_uint(Ab[(rg*16+ly+8)*A_STRIDE + kk+kq+4]);
            #pragma unroll
            for (int nt = 0; nt < 8; nt++){
                const int n = ch*64 + nt*8 + ly;
                uint32_t bb0 = __float_as_uint(Wb[(kk+kq  )*W_STRIDE + n]);
                uint32_t bb1 = __float_as_uint(Wb[(kk+kq+4)*W_STRIDE + n]);
                asm volatile(
                    "mma.sync.aligned.m16n8k8.row.col.f32.tf32.tf32.f32 "
                    "{%0,%1,%2,%3}, {%4,%5,%6,%7}, {%8,%9}, {%0,%1,%2,%3};\n"
                    : "+f"(acc[nt][0]), "+f"(acc[nt][1]),
                      "+f"(acc[nt][2]), "+f"(acc[nt][3])
                    : "r"(a0), "r"(a1), "r"(a2), "r"(a3), "r"(bb0), "r"(bb1));
            }
        }
    }

    // ---- LayerNorm stats ----
    float sA=0.f, qA=0.f, sB=0.f, qB=0.f;
    #pragma unroll
    for (int nt = 0; nt < 8; nt++){
        float x0=acc[nt][0], x1=acc[nt][1], x2=acc[nt][2], x3=acc[nt][3];
        sA += x0+x1; qA += x0*x0 + x1*x1;
        sB += x2+x3; qB += x2*x2 + x3*x3;
    }
    #pragma unroll
    for (int o = 1; o < 4; o <<= 1){
        sA += __shfl_xor_sync(0xffffffffu, sA, o);
        qA += __shfl_xor_sync(0xffffffffu, qA, o);
        sB += __shfl_xor_sync(0xffffffffu, sB, o);
        qB += __shfl_xor_sync(0xffffffffu, qB, o);
    }
    const int r0 = rg*16 + ly, r1 = r0 + 8;
    if (kq == 0){
        red[ch*128 + r0*2    ] = sA;  red[ch*128 + r0*2 + 1] = qA;
        red[ch*128 + r1*2    ] = sB;  red[ch*128 + r1*2 + 1] = qB;
    }
    __syncthreads();   // also: all warps done with MMA -> W buffers reusable as stage

    float s0 = red[r0*2] + red[128 + r0*2] + red[256 + r0*2] + red[384 + r0*2];
    float q0 = red[r0*2+1] + red[128 + r0*2+1] + red[256 + r0*2+1] + red[384 + r0*2+1];
    float s1 = red[r1*2] + red[128 + r1*2] + red[256 + r1*2] + red[384 + r1*2];
    float q1 = red[r1*2+1] + red[128 + r1*2+1] + red[256 + r1*2+1] + red[384 + r1*2+1];
    const float mA = s0 * (1.f/FEAT);
    const float rA = rsqrtf(fmaxf(q0*(1.f/FEAT) - mA*mA, 0.f) + 1e-5f);
    const float mB = s1 * (1.f/FEAT);
    const float rB = rsqrtf(fmaxf(q1*(1.f/FEAT) - mB*mB, 0.f) + 1e-5f);

    // ---- stage normalized tile (stride W_STRIDE, in the W-buffer region) ----
    float* st = Wsm;
    #pragma unroll
    for (int nt = 0; nt < 8; nt++){
        int col = ch*64 + nt*8 + 2*kq;
        float gg0 = gs[col], gg1 = gs[col+1], dd0 = bs[col], dd1 = bs[col+1];
        float2 va, vb;
        va.x = fmaxf(fmaf((acc[nt][0]-mA)*rA, gg0, dd0), 0.f);
        va.y = fmaxf(fmaf((acc[nt][1]-mA)*rA, gg1, dd1), 0.f);
        vb.x = fmaxf(fmaf((acc[nt][2]-mB)*rB, gg0, dd0), 0.f);
        vb.y = fmaxf(fmaf((acc[nt][3]-mB)*rB, gg1, dd1), 0.f);
        *(float2*)&st[r0*W_STRIDE + col] = va;
        *(float2*)&st[r1*W_STRIDE + col] = vb;
    }
    __syncthreads();

    // ---- coalesced streaming writes ----
    float* out_orig = outbase;
    float* out_new  = outbase + (size_t)BATCH*NORIG*FEAT;
    if (mode == 0){
        float* dst = out_new + ((size_t)b*NDOWN + (size_t)(di*DOWN_ + half*64))*FEAT;
        #pragma unroll
        for (int j = 0; j < 8; j++){
            int i = tid + j*THREADS;            // 0..4095
            int row = i >> 6, c4 = i & 63;
            float4 v = *(float4*)&st[row*W_STRIDE + c4*4];
            __stcs((float4*)(dst + row*FEAT + c4*4), v);
        }
    } else {
        const size_t nb = (size_t)b*NORIG;
        #pragma unroll
        for (int j = 0; j < 32; j++){
            int i = tid + j*THREADS;            // 0..16383
            int row = i >> 8;                   // src row 0..63
            int seg = (i >> 7) & 1;             // which orig grid row of the pair
            int off = i & 127;                  // float4 within the 2048B dest segment
            int djg = half*64 + row;
            size_t dr = nb + (size_t)(2*di + seg)*ORIG_ + (size_t)2*djg;
            float4 v = *(float4*)&st[row*W_STRIDE + (off & 63)*4];
            __stcs((float4*)(out_orig + dr*FEAT + off*4), v);
        }
    }
}

extern "C" void kernel_launch(void* const* d_in, const int* in_sizes, int n_in,
                              void* d_out, int out_size)
{
    const float* H_orig = (const float*)d_in[0];
    const float* H_down = (const float*)d_in[1];
    const float* W_o2n  = (const float*)d_in[2];
    const float* W_n2o  = (const float*)d_in[3];
    const float* g_o2n  = (const float*)d_in[4];
    const float* b_o2n  = (const float*)d_in[5];
    const float* g_n2o  = (const float*)d_in[6];
    const float* b_n2o  = (const float*)d_in[7];

    static bool attr_set = false;
    cudaFuncSetAttribute(fused, cudaFuncAttributeMaxDynamicSharedMemorySize, SM_BYTES);
    (void)attr_set;

    prep_w<<<dim3(8,8,2), dim3(32,8)>>>(W_o2n, W_n2o);
    fused<<<2048, THREADS, SM_BYTES>>>(H_orig, H_down,
                                       g_o2n, b_o2n, g_n2o, b_n2o,
                                       (float*)d_out);
}

// round 5
// speedup vs baseline: 2.6131x; 1.0559x over previous
#include <cuda_runtime.h>
#include <cstdint>

#define BATCH   4
#define ORIG_   256
#define NORIG   (ORIG_*ORIG_)     // 65536
#define DOWN_   128
#define NDOWN   (DOWN_*DOWN_)     // 16384
#define FEAT    256
#define TILE_M  64
#define THREADS 256

// SMEM layout (floats)
#define A_STRIDE 36               // banks (4*row + k) -> conflict-free a-frag loads
#define W_STRIDE 264              // k-major W: banks (8*k + n) -> conflict-free b-frags
#define A_BUF    (TILE_M*A_STRIDE)        // 2304
#define W_BUF    (32*W_STRIDE)            // 8448
#define OFF_W    (2*A_BUF)                // 4608
#define OFF_G    (OFF_W + 2*W_BUF)        // 21504
#define OFF_B    (OFF_G + FEAT)           // 21760
#define OFF_RED  (OFF_B + FEAT)           // 22016 (256 float2)
#define SM_FLOATS (OFF_RED + 512)         // 22528
#define SM_BYTES  (SM_FLOATS*4)           // 90112 -> 2 CTAs/SM

__device__ float Wt_dev[2][FEAT*FEAT];   // tf32-rounded, k-major weights

__device__ __forceinline__ float tf32r(float x){
    float r; asm("cvt.rna.tf32.f32 %0, %1;" : "=f"(r) : "f"(x)); return r;
}
__device__ __forceinline__ void cpasync16(uint32_t dst, const void* src){
    asm volatile("cp.async.cg.shared.global [%0], [%1], 16;\n" :: "r"(dst), "l"(src));
}
__device__ __forceinline__ void cpcommit(){ asm volatile("cp.async.commit_group;\n" ::: "memory"); }
__device__ __forceinline__ void cpwait0(){ asm volatile("cp.async.wait_group 0;\n" ::: "memory"); }

__device__ __forceinline__ void mma8(float* c, uint32_t a0, uint32_t a1, uint32_t a2,
                                     uint32_t a3, uint32_t b0, uint32_t b1){
    asm volatile(
        "mma.sync.aligned.m16n8k8.row.col.f32.tf32.tf32.f32 "
        "{%0,%1,%2,%3}, {%4,%5,%6,%7}, {%8,%9}, {%0,%1,%2,%3};\n"
        : "+f"(c[0]), "+f"(c[1]), "+f"(c[2]), "+f"(c[3])
        : "r"(a0), "r"(a1), "r"(a2), "r"(a3), "r"(b0), "r"(b1));
}

// ---- prep: Wt[k][n] = tf32_rn(W[n][k]) (512 KB total; L2-resident) ----
__global__ void prep_w(const float* __restrict__ W0, const float* __restrict__ W1){
    __shared__ float t[32][33];
    const float* W  = blockIdx.z ? W1 : W0;
    float*       Wt = Wt_dev[blockIdx.z];
    int bk = blockIdx.x*32, bn = blockIdx.y*32;
    int tx = threadIdx.x, ty = threadIdx.y;
    #pragma unroll
    for (int j = 0; j < 32; j += 8)
        t[ty+j][tx] = W[(size_t)(bn+ty+j)*FEAT + bk + tx];
    __syncthreads();
    #pragma unroll
    for (int j = 0; j < 32; j += 8)
        Wt[(size_t)(bk+ty+j)*FEAT + bn + tx] = tf32r(t[tx][ty+j]);
}

// mode = blockIdx.x & 1 : 0 = down path (gather-sum -> H_new), 1 = up path (H_down -> 4x fanout)
// 0.5 adjacency weight dropped (LayerNorm is invariant to uniform row scale).
__global__ __launch_bounds__(THREADS, 2)
void fused(const float* __restrict__ Ho, const float* __restrict__ Hd,
           const float* __restrict__ g0v, const float* __restrict__ b0v,
           const float* __restrict__ g1v, const float* __restrict__ b1v,
           float* __restrict__ outbase)
{
    extern __shared__ float sm[];
    float*  Asm  = sm;
    float*  Wsm  = sm + OFF_W;
    float*  gs   = sm + OFF_G;
    float*  bs   = sm + OFF_B;
    float2* red2 = (float2*)(sm + OFF_RED);

    const int tid  = threadIdx.x;
    const int lane = tid & 31;
    const int w    = tid >> 5;
    const int rg   = w & 1;        // 32-row group
    const int ch   = w >> 1;       // 64-col quarter
    const int ly   = lane >> 2;
    const int kq   = lane & 3;

    const int mode = blockIdx.x & 1;
    const int tile = blockIdx.x >> 1;      // 0..1023
    const int b    = tile >> 8;
    const int rem  = tile & 255;
    const int di   = rem >> 1;
    const int half = rem & 1;

    {
        const float* gv = mode ? g1v : g0v;
        const float* bv = mode ? b1v : b0v;
        gs[tid] = gv[tid]; bs[tid] = bv[tid];
    }

    const float* Wt = Wt_dev[mode];
    const uint32_t smb = (uint32_t)__cvta_generic_to_shared(sm);

    float acc[2][8][4];
    #pragma unroll
    for (int t2 = 0; t2 < 2; t2++)
        #pragma unroll
        for (int nt = 0; nt < 8; nt++)
            #pragma unroll
            for (int e = 0; e < 4; e++) acc[t2][nt][e] = 0.f;

    // ---- chunk loaders ----
    auto loadW = [&](int kc){
        const float* src = Wt + (size_t)(kc*32)*FEAT;
        uint32_t base = smb + 4u*(OFF_W + (kc&1)*W_BUF);
        #pragma unroll
        for (int it = 0; it < 8; it++){
            int idx = tid + it*THREADS;          // 0..2047
            int k = idx >> 6, n4 = idx & 63;
            cpasync16(base + 4u*(k*W_STRIDE + n4*4), src + (size_t)k*FEAT + n4*4);
        }
    };
    auto loadA = [&](int kc){
        #pragma unroll
        for (int it = 0; it < 2; it++){
            int idx = tid + it*THREADS;          // 0..511
            int dj = idx >> 3, q = idx & 7;
            if (mode == 0){
                size_t orow = (size_t)b*NORIG + (size_t)(2*di)*ORIG_ + (size_t)2*(half*64 + dj);
                const float4* p = (const float4*)Ho + orow*64 + kc*8 + q;
                float4 v0 = __ldcs(p);
                float4 v1 = __ldcs(p + 64);
                float4 v2 = __ldcs(p + ORIG_*64);
                float4 v3 = __ldcs(p + ORIG_*64 + 64);
                float4 s;
                s.x = tf32r((v0.x+v1.x)+(v2.x+v3.x));
                s.y = tf32r((v0.y+v1.y)+(v2.y+v3.y));
                s.z = tf32r((v0.z+v1.z)+(v2.z+v3.z));
                s.w = tf32r((v0.w+v1.w)+(v2.w+v3.w));
                *(float4*)&Asm[(kc&1)*A_BUF + dj*A_STRIDE + q*4] = s;
            } else {
                size_t drow = (size_t)b*NDOWN + (size_t)(di*DOWN_ + half*64 + dj);
                cpasync16(smb + 4u*((kc&1)*A_BUF + dj*A_STRIDE + q*4),
                          Hd + drow*FEAT + kc*32 + q*4);
            }
        }
    };

    // ---- pipelined mainloop: 8 K-chunks, double buffered ----
    loadW(0); loadA(0); cpcommit();

    for (int kc = 0; kc < 8; kc++){
        cpwait0();
        __syncthreads();
        if (kc < 7){ loadW(kc+1); loadA(kc+1); cpcommit(); }

        const float* Ab = Asm + (kc&1)*A_BUF;
        const float* Wb = Wsm + (kc&1)*W_BUF;
        #pragma unroll
        for (int ks = 0; ks < 4; ks++){
            const int kk = ks*8;
            const int r0 = rg*32 + ly;
            uint32_t a0 = __float_as_uint(Ab[(r0    )*A_STRIDE + kk+kq  ]);
            uint32_t a1 = __float_as_uint(Ab[(r0+ 8 )*A_STRIDE + kk+kq  ]);
            uint32_t a2 = __float_as_uint(Ab[(r0    )*A_STRIDE + kk+kq+4]);
            uint32_t a3 = __float_as_uint(Ab[(r0+ 8 )*A_STRIDE + kk+kq+4]);
            uint32_t a4 = __float_as_uint(Ab[(r0+16 )*A_STRIDE + kk+kq  ]);
            uint32_t a5 = __float_as_uint(Ab[(r0+24 )*A_STRIDE + kk+kq  ]);
            uint32_t a6 = __float_as_uint(Ab[(r0+16 )*A_STRIDE + kk+kq+4]);
            uint32_t a7 = __float_as_uint(Ab[(r0+24 )*A_STRIDE + kk+kq+4]);
            #pragma unroll
            for (int nt = 0; nt < 8; nt++){
                const int n = ch*64 + nt*8 + ly;
                uint32_t bb0 = __float_as_uint(Wb[(kk+kq  )*W_STRIDE + n]);
                uint32_t bb1 = __float_as_uint(Wb[(kk+kq+4)*W_STRIDE + n]);
                mma8(acc[0][nt], a0, a1, a2, a3, bb0, bb1);   // B regs reused: 2 m-tiles
                mma8(acc[1][nt], a4, a5, a6, a7, bb0, bb1);
            }
        }
    }

    // ---- LayerNorm stats (4 rows per thread) ----
    const int rr[4] = { rg*32 + ly, rg*32 + ly + 8, rg*32 + ly + 16, rg*32 + ly + 24 };
    float s[4] = {0.f,0.f,0.f,0.f}, qs[4] = {0.f,0.f,0.f,0.f};
    #pragma unroll
    for (int t2 = 0; t2 < 2; t2++)
        #pragma unroll
        for (int nt = 0; nt < 8; nt++){
            float x0=acc[t2][nt][0], x1=acc[t2][nt][1];
            float x2=acc[t2][nt][2], x3=acc[t2][nt][3];
            s[2*t2]   += x0+x1;  qs[2*t2]   += x0*x0 + x1*x1;
            s[2*t2+1] += x2+x3;  qs[2*t2+1] += x2*x2 + x3*x3;
        }
    #pragma unroll
    for (int o = 1; o < 4; o <<= 1)
        #pragma unroll
        for (int j = 0; j < 4; j++){
            s[j]  += __shfl_xor_sync(0xffffffffu, s[j],  o);
            qs[j] += __shfl_xor_sync(0xffffffffu, qs[j], o);
        }
    if (kq == 0){
        #pragma unroll
        for (int j = 0; j < 4; j++) red2[ch*64 + rr[j]] = make_float2(s[j], qs[j]);
    }
    __syncthreads();   // also fences MMA reads -> W buffers reusable as staging

    float mean[4], rstd[4];
    #pragma unroll
    for (int j = 0; j < 4; j++){
        float2 p0 = red2[rr[j]], p1 = red2[64+rr[j]], p2 = red2[128+rr[j]], p3 = red2[192+rr[j]];
        float ss = (p0.x+p1.x)+(p2.x+p3.x);
        float qq = (p0.y+p1.y)+(p2.y+p3.y);
        mean[j] = ss * (1.f/FEAT);
        rstd[j] = rsqrtf(fmaxf(qq*(1.f/FEAT) - mean[j]*mean[j], 0.f) + 1e-5f);
    }

    // ---- stage normalized tile (stride W_STRIDE, in the W-buffer region) ----
    float* st = Wsm;
    #pragma unroll
    for (int t2 = 0; t2 < 2; t2++)
        #pragma unroll
        for (int nt = 0; nt < 8; nt++){
            int col = ch*64 + nt*8 + 2*kq;
            float gg0 = gs[col], gg1 = gs[col+1], dd0 = bs[col], dd1 = bs[col+1];
            int jl = 2*t2, jh = 2*t2+1;
            float2 va, vb;
            va.x = fmaxf(fmaf((acc[t2][nt][0]-mean[jl])*rstd[jl], gg0, dd0), 0.f);
            va.y = fmaxf(fmaf((acc[t2][nt][1]-mean[jl])*rstd[jl], gg1, dd1), 0.f);
            vb.x = fmaxf(fmaf((acc[t2][nt][2]-mean[jh])*rstd[jh], gg0, dd0), 0.f);
            vb.y = fmaxf(fmaf((acc[t2][nt][3]-mean[jh])*rstd[jh], gg1, dd1), 0.f);
            *(float2*)&st[rr[jl]*W_STRIDE + col] = va;
            *(float2*)&st[rr[jh]*W_STRIDE + col] = vb;
        }
    __syncthreads();

    // ---- coalesced streaming stores ----
    float* out_orig = outbase;
    float* out_new  = outbase + (size_t)BATCH*NORIG*FEAT;
    if (mode == 0){
        float* dst = out_new + ((size_t)b*NDOWN + (size_t)(di*DOWN_ + half*64))*FEAT;
        #pragma unroll
        for (int j = 0; j < 16; j++){
            int i = tid + j*THREADS;            // 0..4095
            int row = i >> 6, c4 = i & 63;
            float4 v = *(float4*)&st[row*W_STRIDE + c4*4];
            __stcs((float4*)(dst + row*FEAT + c4*4), v);
        }
    } else {
        const size_t nb = (size_t)b*NORIG;
        #pragma unroll
        for (int j = 0; j < 64; j++){
            int i = tid + j*THREADS;            // 0..16383
            int row = i >> 8;                   // src row 0..63
            int seg = (i >> 7) & 1;             // which orig grid row of the pair
            int off = i & 127;                  // float4 within 2048B dest segment
            int djg = half*64 + row;
            size_t dr = nb + (size_t)(2*di + seg)*ORIG_ + (size_t)2*djg;
            float4 v = *(float4*)&st[row*W_STRIDE + (off & 63)*4];
            __stcs((float4*)(out_orig + dr*FEAT + off*4), v);
        }
    }
}

extern "C" void kernel_launch(void* const* d_in, const int* in_sizes, int n_in,
                              void* d_out, int out_size)
{
    const float* H_orig = (const float*)d_in[0];
    const float* H_down = (const float*)d_in[1];
    const float* W_o2n  = (const float*)d_in[2];
    const float* W_n2o  = (const float*)d_in[3];
    const float* g_o2n  = (const float*)d_in[4];
    const float* b_o2n  = (const float*)d_in[5];
    const float* g_n2o  = (const float*)d_in[6];
    const float* b_n2o  = (const float*)d_in[7];

    cudaFuncSetAttribute(fused, cudaFuncAttributeMaxDynamicSharedMemorySize, SM_BYTES);

    prep_w<<<dim3(8,8,2), dim3(32,8)>>>(W_o2n, W_n2o);
    fused<<<2048, THREADS, SM_BYTES>>>(H_orig, H_down,
                                       g_o2n, b_o2n, g_n2o, b_n2o,
                                       (float*)d_out);
}

// round 6
// speedup vs baseline: 2.6638x; 1.0194x over previous
#include <cuda_runtime.h>
#include <cstdint>

#define BATCH   4
#define ORIG_   256
#define NORIG   (ORIG_*ORIG_)     // 65536
#define DOWN_   128
#define NDOWN   (DOWN_*DOWN_)     // 16384
#define FEAT    256
#define TILE_M  64
#define THREADS 512

// SMEM layout (floats)
#define A_STRIDE 36               // conflict-free a-frag loads
#define W_STRIDE 264              // k-major W: conflict-free b-frag loads
#define A_BUF    (TILE_M*A_STRIDE)        // 2304
#define W_BUF    (32*W_STRIDE)            // 8448
#define OFF_W    (2*A_BUF)                // 4608
#define OFF_G    (OFF_W + 2*W_BUF)        // 21504
#define OFF_B    (OFF_G + FEAT)           // 21760
#define OFF_RED  (OFF_B + FEAT)           // 22016 (8*64 float2 = 1024 floats)
#define SM_FLOATS (OFF_RED + 1024)        // 23040
#define SM_BYTES  (SM_FLOATS*4)           // 92160 -> 2 CTAs/SM

__device__ float Wt_dev[2][FEAT*FEAT];   // tf32-rounded, k-major weights

__device__ __forceinline__ float tf32r(float x){
    float r; asm("cvt.rna.tf32.f32 %0, %1;" : "=f"(r) : "f"(x)); return r;
}
__device__ __forceinline__ void cpasync16(uint32_t dst, const void* src){
    asm volatile("cp.async.cg.shared.global [%0], [%1], 16;\n" :: "r"(dst), "l"(src));
}
__device__ __forceinline__ void cpcommit(){ asm volatile("cp.async.commit_group;\n" ::: "memory"); }
__device__ __forceinline__ void cpwait0(){ asm volatile("cp.async.wait_group 0;\n" ::: "memory"); }

__device__ __forceinline__ void mma8(float* c, uint32_t a0, uint32_t a1, uint32_t a2,
                                     uint32_t a3, uint32_t b0, uint32_t b1){
    asm volatile(
        "mma.sync.aligned.m16n8k8.row.col.f32.tf32.tf32.f32 "
        "{%0,%1,%2,%3}, {%4,%5,%6,%7}, {%8,%9}, {%0,%1,%2,%3};\n"
        : "+f"(c[0]), "+f"(c[1]), "+f"(c[2]), "+f"(c[3])
        : "r"(a0), "r"(a1), "r"(a2), "r"(a3), "r"(b0), "r"(b1));
}

// ---- prep: Wt[k][n] = tf32_rn(W[n][k]) (512 KB total; L2-resident) ----
__global__ void prep_w(const float* __restrict__ W0, const float* __restrict__ W1){
    __shared__ float t[32][33];
    const float* W  = blockIdx.z ? W1 : W0;
    float*       Wt = Wt_dev[blockIdx.z];
    int bk = blockIdx.x*32, bn = blockIdx.y*32;
    int tx = threadIdx.x, ty = threadIdx.y;
    #pragma unroll
    for (int j = 0; j < 32; j += 8)
        t[ty+j][tx] = W[(size_t)(bn+ty+j)*FEAT + bk + tx];
    __syncthreads();
    #pragma unroll
    for (int j = 0; j < 32; j += 8)
        Wt[(size_t)(bk+ty+j)*FEAT + bn + tx] = tf32r(t[tx][ty+j]);
}

// mode = blockIdx.x & 1 : 0 = down path (gather-sum -> H_new), 1 = up path (H_down -> 4x fanout)
// 0.5 adjacency weight dropped (LayerNorm is invariant to uniform row scale).
__global__ __launch_bounds__(THREADS, 2)
void fused(const float* __restrict__ Ho, const float* __restrict__ Hd,
           const float* __restrict__ g0v, const float* __restrict__ b0v,
           const float* __restrict__ g1v, const float* __restrict__ b1v,
           float* __restrict__ outbase)
{
    extern __shared__ float sm[];
    float*  Asm  = sm;
    float*  Wsm  = sm + OFF_W;
    float*  gs   = sm + OFF_G;
    float*  bs   = sm + OFF_B;
    float2* red2 = (float2*)(sm + OFF_RED);

    const int tid  = threadIdx.x;
    const int lane = tid & 31;
    const int w    = tid >> 5;
    const int rg   = w & 1;        // 32-row group
    const int ch   = w >> 1;       // 32-col eighth (0..7)
    const int ly   = lane >> 2;
    const int kq   = lane & 3;

    const int mode = blockIdx.x & 1;
    const int tile = blockIdx.x >> 1;      // 0..1023
    const int b    = tile >> 8;
    const int rem  = tile & 255;
    const int di   = rem >> 1;
    const int half = rem & 1;

    if (tid < FEAT){
        const float* gv = mode ? g1v : g0v;
        const float* bv = mode ? b1v : b0v;
        gs[tid] = gv[tid]; bs[tid] = bv[tid];
    }

    const float* Wt = Wt_dev[mode];
    const uint32_t smb = (uint32_t)__cvta_generic_to_shared(sm);

    float acc[2][4][4];
    #pragma unroll
    for (int t2 = 0; t2 < 2; t2++)
        #pragma unroll
        for (int nt = 0; nt < 4; nt++)
            #pragma unroll
            for (int e = 0; e < 4; e++) acc[t2][nt][e] = 0.f;

    // ---- chunk loaders ----
    auto loadW = [&](int kc){
        const float* src = Wt + (size_t)(kc*32)*FEAT;
        uint32_t base = smb + 4u*(OFF_W + (kc&1)*W_BUF);
        #pragma unroll
        for (int it = 0; it < 4; it++){
            int idx = tid + it*THREADS;          // 0..2047
            int k = idx >> 6, n4 = idx & 63;
            cpasync16(base + 4u*(k*W_STRIDE + n4*4), src + (size_t)k*FEAT + n4*4);
        }
    };
    auto loadA = [&](int kc){
        int dj = tid >> 3, q = tid & 7;          // 64 rows x 8 float4
        if (mode == 0){
            size_t orow = (size_t)b*NORIG + (size_t)(2*di)*ORIG_ + (size_t)2*(half*64 + dj);
            const float4* p = (const float4*)Ho + orow*64 + kc*8 + q;
            float4 v0 = __ldcs(p);
            float4 v1 = __ldcs(p + 64);
            float4 v2 = __ldcs(p + ORIG_*64);
            float4 v3 = __ldcs(p + ORIG_*64 + 64);
            float4 s;
            s.x = tf32r((v0.x+v1.x)+(v2.x+v3.x));
            s.y = tf32r((v0.y+v1.y)+(v2.y+v3.y));
            s.z = tf32r((v0.z+v1.z)+(v2.z+v3.z));
            s.w = tf32r((v0.w+v1.w)+(v2.w+v3.w));
            *(float4*)&Asm[(kc&1)*A_BUF + dj*A_STRIDE + q*4] = s;
        } else {
            size_t drow = (size_t)b*NDOWN + (size_t)(di*DOWN_ + half*64 + dj);
            cpasync16(smb + 4u*((kc&1)*A_BUF + dj*A_STRIDE + q*4),
                      Hd + drow*FEAT + kc*32 + q*4);
        }
    };

    // ---- pipelined mainloop: 8 K-chunks, double buffered ----
    loadW(0); loadA(0); cpcommit();

    for (int kc = 0; kc < 8; kc++){
        cpwait0();
        __syncthreads();
        if (kc < 7){ loadW(kc+1); loadA(kc+1); cpcommit(); }

        const float* Ab = Asm + (kc&1)*A_BUF;
        const float* Wb = Wsm + (kc&1)*W_BUF;
        #pragma unroll
        for (int ks = 0; ks < 4; ks++){
            const int kk = ks*8;
            const int r0 = rg*32 + ly;
            uint32_t a0 = __float_as_uint(Ab[(r0    )*A_STRIDE + kk+kq  ]);
            uint32_t a1 = __float_as_uint(Ab[(r0+ 8 )*A_STRIDE + kk+kq  ]);
            uint32_t a2 = __float_as_uint(Ab[(r0    )*A_STRIDE + kk+kq+4]);
            uint32_t a3 = __float_as_uint(Ab[(r0+ 8 )*A_STRIDE + kk+kq+4]);
            uint32_t a4 = __float_as_uint(Ab[(r0+16 )*A_STRIDE + kk+kq  ]);
            uint32_t a5 = __float_as_uint(Ab[(r0+24 )*A_STRIDE + kk+kq  ]);
            uint32_t a6 = __float_as_uint(Ab[(r0+16 )*A_STRIDE + kk+kq+4]);
            uint32_t a7 = __float_as_uint(Ab[(r0+24 )*A_STRIDE + kk+kq+4]);
            #pragma unroll
            for (int nt = 0; nt < 4; nt++){
                const int n = ch*32 + nt*8 + ly;
                uint32_t bb0 = __float_as_uint(Wb[(kk+kq  )*W_STRIDE + n]);
                uint32_t bb1 = __float_as_uint(Wb[(kk+kq+4)*W_STRIDE + n]);
                mma8(acc[0][nt], a0, a1, a2, a3, bb0, bb1);   // B regs reused: 2 m-tiles
                mma8(acc[1][nt], a4, a5, a6, a7, bb0, bb1);
            }
        }
    }

    // ---- LayerNorm stats (4 rows per thread) ----
    const int rr0 = rg*32 + ly;
    float s[4] = {0.f,0.f,0.f,0.f}, qs[4] = {0.f,0.f,0.f,0.f};
    #pragma unroll
    for (int t2 = 0; t2 < 2; t2++)
        #pragma unroll
        for (int nt = 0; nt < 4; nt++){
            float x0=acc[t2][nt][0], x1=acc[t2][nt][1];
            float x2=acc[t2][nt][2], x3=acc[t2][nt][3];
            s[2*t2]   += x0+x1;  qs[2*t2]   += x0*x0 + x1*x1;
            s[2*t2+1] += x2+x3;  qs[2*t2+1] += x2*x2 + x3*x3;
        }
    #pragma unroll
    for (int o = 1; o < 4; o <<= 1)
        #pragma unroll
        for (int j = 0; j < 4; j++){
            s[j]  += __shfl_xor_sync(0xffffffffu, s[j],  o);
            qs[j] += __shfl_xor_sync(0xffffffffu, qs[j], o);
        }
    if (kq == 0){
        #pragma unroll
        for (int j = 0; j < 4; j++){
            int row = rr0 + ((j&1)?8:0) + ((j>>1)?16:0);
            red2[ch*64 + row] = make_float2(s[j], qs[j]);
        }
    }
    __syncthreads();   // also fences MMA reads -> W buffers reusable as staging

    float mean[4], rstd[4];
    #pragma unroll
    for (int j = 0; j < 4; j++){
        int row = rr0 + ((j&1)?8:0) + ((j>>1)?16:0);
        float ss = 0.f, qq = 0.f;
        #pragma unroll
        for (int p = 0; p < 8; p++){
            float2 pr = red2[p*64 + row];
            ss += pr.x; qq += pr.y;
        }
        mean[j] = ss * (1.f/FEAT);
        rstd[j] = rsqrtf(fmaxf(qq*(1.f/FEAT) - mean[j]*mean[j], 0.f) + 1e-5f);
    }

    // ---- stage normalized tile (stride W_STRIDE, in the W-buffer region) ----
    float* st = Wsm;
    #pragma unroll
    for (int t2 = 0; t2 < 2; t2++)
        #pragma unroll
        for (int nt = 0; nt < 4; nt++){
            int col = ch*32 + nt*8 + 2*kq;
            float gg0 = gs[col], gg1 = gs[col+1], dd0 = bs[col], dd1 = bs[col+1];
            int jl = 2*t2, jh = 2*t2+1;
            int rl = rr0 + (t2?16:0), rh = rl + 8;
            float2 va, vb;
            va.x = fmaxf(fmaf((acc[t2][nt][0]-mean[jl])*rstd[jl], gg0, dd0), 0.f);
            va.y = fmaxf(fmaf((acc[t2][nt][1]-mean[jl])*rstd[jl], gg1, dd1), 0.f);
            vb.x = fmaxf(fmaf((acc[t2][nt][2]-mean[jh])*rstd[jh], gg0, dd0), 0.f);
            vb.y = fmaxf(fmaf((acc[t2][nt][3]-mean[jh])*rstd[jh], gg1, dd1), 0.f);
            *(float2*)&st[rl*W_STRIDE + col] = va;
            *(float2*)&st[rh*W_STRIDE + col] = vb;
        }
    __syncthreads();

    // ---- coalesced streaming stores ----
    float* out_orig = outbase;
    float* out_new  = outbase + (size_t)BATCH*NORIG*FEAT;
    if (mode == 0){
        float* dst = out_new + ((size_t)b*NDOWN + (size_t)(di*DOWN_ + half*64))*FEAT;
        #pragma unroll
        for (int j = 0; j < 8; j++){
            int i = tid + j*THREADS;            // 0..4095
            int row = i >> 6, c4 = i & 63;
            float4 v = *(float4*)&st[row*W_STRIDE + c4*4];
            __stcs((float4*)(dst + row*FEAT + c4*4), v);
        }
    } else {
        const size_t nb = (size_t)b*NORIG;
        #pragma unroll
        for (int j = 0; j < 32; j++){
            int i = tid + j*THREADS;            // 0..16383
            int row = i >> 8;                   // src row 0..63
            int seg = (i >> 7) & 1;             // which orig grid row of the pair
            int off = i & 127;                  // float4 within 2048B dest segment
            int djg = half*64 + row;
            size_t dr = nb + (size_t)(2*di + seg)*ORIG_ + (size_t)2*djg;
            float4 v = *(float4*)&st[row*W_STRIDE + (off & 63)*4];
            __stcs((float4*)(out_orig + dr*FEAT + off*4), v);
        }
    }
}

extern "C" void kernel_launch(void* const* d_in, const int* in_sizes, int n_in,
                              void* d_out, int out_size)
{
    const float* H_orig = (const float*)d_in[0];
    const float* H_down = (const float*)d_in[1];
    const float* W_o2n  = (const float*)d_in[2];
    const float* W_n2o  = (const float*)d_in[3];
    const float* g_o2n  = (const float*)d_in[4];
    const float* b_o2n  = (const float*)d_in[5];
    const float* g_n2o  = (const float*)d_in[6];
    const float* b_n2o  = (const float*)d_in[7];

    cudaFuncSetAttribute(fused, cudaFuncAttributeMaxDynamicSharedMemorySize, SM_BYTES);

    prep_w<<<dim3(8,8,2), dim3(32,8)>>>(W_o2n, W_n2o);
    fused<<<2048, THREADS, SM_BYTES>>>(H_orig, H_down,
                                       g_o2n, b_o2n, g_n2o, b_n2o,
                                       (float*)d_out);
}